// round 3
// baseline (speedup 1.0000x reference)
#include <cuda_runtime.h>
#include <math.h>
#include <float.h>

#define B_ROWS 4096
#define C_COLS 128
#define WARPS_PER_BLOCK 32
#define NBLOCKS (B_ROWS / WARPS_PER_BLOCK)   // 128  -> single wave on 148 SMs

// Per-block partials [bce, wlsep, pos] and completion counter.
__device__ float g_partial[NBLOCKS * 3];
__device__ unsigned int g_count;

__device__ __forceinline__ float softplus_fast(float t) {
    // log(1 + exp(t)) with MUFU-only math; arg of __logf is in [1,2] -> accurate.
    return fmaxf(t, 0.0f) + __logf(1.0f + __expf(-fabsf(t)));
}

__device__ __forceinline__ float warp_sum(float v) {
    #pragma unroll
    for (int o = 16; o > 0; o >>= 1)
        v += __shfl_xor_sync(0xFFFFFFFFu, v, o);
    return v;
}

__device__ __forceinline__ float warp_max(float v) {
    #pragma unroll
    for (int o = 16; o > 0; o >>= 1)
        v = fmaxf(v, __shfl_xor_sync(0xFFFFFFFFu, v, o));
    return v;
}

__global__ void __launch_bounds__(32 * WARPS_PER_BLOCK)
fused_kernel(const float* __restrict__ x, const int* __restrict__ tgt,
             float* __restrict__ out) {
    const int warp = threadIdx.y;
    const int lane = threadIdx.x;
    const int tid  = warp * 32 + lane;
    const int row  = blockIdx.x * WARPS_PER_BLOCK + warp;

    // one LDG.128 per operand per warp
    const float4 xv = ((const float4*)(x   + (size_t)row * C_COLS))[lane];
    const int4   lv = ((const int4*)  (tgt + (size_t)row * C_COLS))[lane];
    float xs[4] = {xv.x, xv.y, xv.z, xv.w};
    int   ls[4] = {lv.x, lv.y, lv.z, lv.w};

    // ---- BCE + negative-class max + positive count (ballot) ----
    float bce  = 0.0f;
    float mneg = -FLT_MAX;
    int   npos = 0;
    #pragma unroll
    for (int k = 0; k < 4; k++) {
        float t = ls[k] ? -xs[k] : xs[k];
        bce += softplus_fast(t);
        if (!ls[k]) mneg = fmaxf(mneg, xs[k]);
        npos += __popc(__ballot_sync(0xFFFFFFFFu, ls[k] != 0));
    }
    mneg = warp_max(mneg);

    // ---- Z = sum over negatives of exp(x_i - M) ----
    float z = 0.0f;
    #pragma unroll
    for (int k = 0; k < 4; k++)
        if (!ls[k]) z += __expf(xs[k] - mneg);
    z = warp_sum(z);

    // ---- per-positive lse_j = m + log(e^-m + Z*e^{M-x_j-m}), m=max(0,M-x_j) ----
    float wl = 0.0f;
    #pragma unroll
    for (int k = 0; k < 4; k++) {
        if (ls[k]) {
            float d = mneg - xs[k];
            float m = fmaxf(0.0f, d);
            wl += m + __logf(__expf(-m) + z * __expf(d - m));
        }
    }

    bce = warp_sum(bce);
    wl  = warp_sum(wl);

    // ---- block reduction over 32 warps ----
    __shared__ float s_b[WARPS_PER_BLOCK];
    __shared__ float s_w[WARPS_PER_BLOCK];
    __shared__ float s_p[WARPS_PER_BLOCK];
    if (lane == 0) {
        s_b[warp] = bce;
        s_w[warp] = wl;
        s_p[warp] = (float)npos;   // npos is uniform across the warp (ballot)
    }
    __syncthreads();

    __shared__ bool is_last;
    if (warp == 0) {
        float b = warp_sum(s_b[lane]);
        float w = warp_sum(s_w[lane]);
        float p = warp_sum(s_p[lane]);
        if (lane == 0) {
            g_partial[blockIdx.x * 3 + 0] = b;
            g_partial[blockIdx.x * 3 + 1] = w;
            g_partial[blockIdx.x * 3 + 2] = p;
            __threadfence();
            unsigned int v = atomicAdd(&g_count, 1u);
            is_last = (v == (unsigned)(gridDim.x - 1));
        }
    }
    __syncthreads();

    // ---- last block reduces all partials (fixed order -> deterministic) ----
    if (is_last) {
        __shared__ float r_b[NBLOCKS], r_w[NBLOCKS], r_p[NBLOCKS];
        const volatile float* gp = g_partial;
        if (tid < NBLOCKS) {
            r_b[tid] = gp[tid * 3 + 0];
            r_w[tid] = gp[tid * 3 + 1];
            r_p[tid] = gp[tid * 3 + 2];
        }
        __syncthreads();
        #pragma unroll
        for (int stride = NBLOCKS / 2; stride > 0; stride >>= 1) {
            if (tid < stride) {
                r_b[tid] += r_b[tid + stride];
                r_w[tid] += r_w[tid + stride];
                r_p[tid] += r_p[tid + stride];
            }
            __syncthreads();
        }
        if (tid == 0) {
            out[0] = r_b[0] / (float)(B_ROWS * C_COLS) + r_w[0] / r_p[0];
            g_count = 0;   // reset for next graph replay
        }
    }
}

extern "C" void kernel_launch(void* const* d_in, const int* in_sizes, int n_in,
                              void* d_out, int out_size) {
    (void)in_sizes; (void)n_in; (void)out_size;
    const float* x   = (const float*)d_in[0];
    const int*   tgt = (const int*)d_in[1];
    float*       out = (float*)d_out;

    dim3 blk(32, WARPS_PER_BLOCK);
    fused_kernel<<<NBLOCKS, blk>>>(x, tgt, out);
}